// round 11
// baseline (speedup 1.0000x reference)
#include <cuda_runtime.h>
#include <cuda_fp16.h>
#include <cstdint>

// ---------------- problem constants ----------------
#define CC   128
#define HH   96
#define WW   128
#define PP   (HH * WW)      // 12288 (M)
#define HRR  96
#define WRR  128
#define QQ   (HRR * WRR)    // 12288 (N)

// ---------------- tiling ----------------
#define BM    128           // CTA m-tile
#define BN    256           // CTA n-tile
#define NQT   (QQ / BN)     // 48 q-tiles
#define NS    3             // n-splits (grid.y) -> 288 CTAs = 2 waves @ 94.7%
#define TPC   (NQT / NS)    // 16 tiles per CTA

#define A_IMG_BYTES   32768                  // one A variant image per mt (fragment-ready)
#define B_IMG_BYTES   65536                  // one B variant image per qt (fragment-ready)
#define B_HALF_BYTES  32768                  // one k-half of a B variant image
#define SMEM_A_OFF    1024
#define SMEM_B_OFF    (SMEM_A_OFF + 2 * A_IMG_BYTES)       // 66560
#define SMEM_TOTAL    (SMEM_B_OFF + 4 * B_HALF_BYTES)      // 197632

// ---------------- device scratch (no allocs allowed) ----------------
// A: [mt 96][variant 2][s 8][mf 8][lane 32] uint4  (fragment-ready fp16 pairs)
__device__ uint4 gA4[96 * 2 * 8 * 8 * 32];
// B: [qt 48][variant 2][s 8][wn 4][r4 4][lane 32] uint4 (fragment-ready, lane-contiguous)
// s-major => a k-half (s 0..3 or 4..7) is a contiguous 32KB block.
__device__ uint4 gB4[48 * 2 * 8 * 4 * 4 * 32];
__device__ unsigned long long g_best[PP];

// ---------------- helpers ----------------
__device__ __forceinline__ uint32_t smem_u32(const void* p) {
    uint32_t a;
    asm("{ .reg .u64 t; cvta.to.shared.u64 t, %1; cvt.u32.u64 %0, t; }" : "=r"(a) : "l"(p));
    return a;
}
__device__ __forceinline__ unsigned int fkey(float f) {
    unsigned int b = __float_as_uint(f);
    return (b & 0x80000000u) ? ~b : (b | 0x80000000u);
}
__device__ __forceinline__ unsigned short h16(float x) {
    __half h = __float2half_rn(x);
    return *reinterpret_cast<unsigned short*>(&h);
}
__device__ __forceinline__ float h16v(unsigned short b) {
    __half h = *reinterpret_cast<__half*>(&b);
    return __half2float(h);
}
// 2-term fp16 split: a = hi + lo (+ ~2^-22 residual)
__device__ __forceinline__ void split2(float a, unsigned short& hi, unsigned short& lo) {
    hi = h16(a);
    lo = h16(a - h16v(hi));
}

// ---------------- mbarrier ----------------
#define MBAR_INIT(a, n) \
    asm volatile("mbarrier.init.shared.b64 [%0], %1;" :: "r"(a), "r"((uint32_t)(n)) : "memory")
#define MBAR_EXPECT_TX(a, n) \
    asm volatile("mbarrier.arrive.expect_tx.shared.b64 _, [%0], %1;" :: "r"(a), "r"((uint32_t)(n)) : "memory")
#define MBAR_ARRIVE(a) \
    asm volatile("mbarrier.arrive.shared.b64 _, [%0];" :: "r"(a) : "memory")

__device__ __forceinline__ void mbar_wait(uint32_t mbar, uint32_t phase) {
    asm volatile(
        "{\n\t.reg .pred P1;\n\t"
        "W_%=:\n\t"
        "mbarrier.try_wait.parity.acquire.cta.shared::cta.b64 P1, [%0], %1, 0x989680;\n\t"
        "@P1 bra.uni D_%=;\n\t"
        "bra.uni W_%=;\n\t"
        "D_%=:\n\t}"
        :: "r"(mbar), "r"(phase) : "memory");
}

__device__ __forceinline__ void issue_cp(uint32_t dst, const char* src, uint32_t fullb) {
    MBAR_EXPECT_TX(fullb, B_HALF_BYTES);
    asm volatile(
        "cp.async.bulk.shared::cluster.global.mbarrier::complete_tx::bytes "
        "[%0], [%1], %2, [%3];"
        :: "r"(dst), "l"(src), "r"((uint32_t)B_HALF_BYTES), "r"(fullb) : "memory");
}

// ---------------- legacy tensor-core mma (baseline PTX, sm_103-safe) ----------------
__device__ __forceinline__ void mma16816(float* d, uint32_t a0, uint32_t a1, uint32_t a2,
                                         uint32_t a3, uint32_t b0, uint32_t b1) {
    asm volatile(
        "mma.sync.aligned.m16n8k16.row.col.f32.f16.f16.f32 "
        "{%0,%1,%2,%3}, {%4,%5,%6,%7}, {%8,%9}, {%0,%1,%2,%3};"
        : "+f"(d[0]), "+f"(d[1]), "+f"(d[2]), "+f"(d[3])
        : "r"(a0), "r"(a1), "r"(a2), "r"(a3), "r"(b0), "r"(b1));
}

// ---------------- precompute: fragment-ready fp16 splits ----------------
__global__ void splitA_kernel(const float* __restrict__ fl) {
    int idx = blockIdx.x * 256 + threadIdx.x;          // 96*8*8*32 = 196608
    int lane = idx & 31, mf = (idx >> 5) & 7, s = (idx >> 8) & 7, mt = idx >> 11;
    int g = lane >> 2, t = lane & 3;
    int M = mt * 128 + mf * 16 + g;
    int K = s * 16 + 2 * t;
    // reg order: (M,K)(M,K+1) | (M+8,K)(M+8,K+1) | (M,K+8)(M,K+9) | (M+8,K+8)(M+8,K+9)
    float v[8];
    v[0] = fl[(size_t)K * PP + M];           v[1] = fl[(size_t)(K + 1) * PP + M];
    v[2] = fl[(size_t)K * PP + M + 8];       v[3] = fl[(size_t)(K + 1) * PP + M + 8];
    v[4] = fl[(size_t)(K + 8) * PP + M];     v[5] = fl[(size_t)(K + 9) * PP + M];
    v[6] = fl[(size_t)(K + 8) * PP + M + 8]; v[7] = fl[(size_t)(K + 9) * PP + M + 8];
    unsigned short hh[8], ll[8];
    #pragma unroll
    for (int k = 0; k < 8; ++k) split2(v[k], hh[k], ll[k]);
    size_t base = ((size_t)(mt * 2) * 8 + s) * 8 + mf;   // variant stride = 64 (s,mf) units
    #pragma unroll
    for (int va = 0; va < 2; ++va) {
        const unsigned short* p = (va == 0) ? hh : ll;
        uint4 o;
        o.x = ((uint32_t)p[1] << 16) | p[0];
        o.y = ((uint32_t)p[3] << 16) | p[2];
        o.z = ((uint32_t)p[5] << 16) | p[4];
        o.w = ((uint32_t)p[7] << 16) | p[6];
        gA4[(base + (size_t)va * 64) * 32 + lane] = o;
    }
}

__global__ void splitB_kernel(const float* __restrict__ fr) {
    int idx = blockIdx.x * 256 + threadIdx.x;          // 48*8*4*4*32 = 196608
    int lane = idx & 31, r4 = (idx >> 5) & 3, wn = (idx >> 7) & 3;
    int s = (idx >> 9) & 7, qt = idx >> 12;
    int g = lane >> 2, t = lane & 3;
    int k0 = s * 16 + 2 * t;
    uint32_t regs[2][4];                                // [variant][j0b0,j0b1,j1b0,j1b1]
    #pragma unroll
    for (int h2 = 0; h2 < 2; ++h2) {
        int j = 2 * r4 + h2;
        int n = qt * 256 + wn * 64 + j * 8 + g;
        float v0 = fr[(size_t)k0 * QQ + n];
        float v1 = fr[(size_t)(k0 + 1) * QQ + n];
        float v8 = fr[(size_t)(k0 + 8) * QQ + n];
        float v9 = fr[(size_t)(k0 + 9) * QQ + n];
        unsigned short h0[2], h1[2], h8[2], h9[2];
        split2(v0, h0[0], h0[1]);
        split2(v1, h1[0], h1[1]);
        split2(v8, h8[0], h8[1]);
        split2(v9, h9[0], h9[1]);
        #pragma unroll
        for (int vv = 0; vv < 2; ++vv) {
            regs[vv][2 * h2]     = ((uint32_t)h1[vv] << 16) | h0[vv];   // b0: (k0,n)(k0+1,n)
            regs[vv][2 * h2 + 1] = ((uint32_t)h9[vv] << 16) | h8[vv];   // b1: (k0+8..9,n)
        }
    }
    #pragma unroll
    for (int vv = 0; vv < 2; ++vv) {
        // lane-contiguous: [qt][vv][s][wn][r4][lane]
        size_t o = ((((size_t)(qt * 2 + vv) * 8 + s) * 4 + wn) * 4 + r4) * 32 + lane;
        gB4[o] = make_uint4(regs[vv][0], regs[vv][1], regs[vv][2], regs[vv][3]);
    }
}

__global__ void init_best_kernel() {
    int p = blockIdx.x * blockDim.x + threadIdx.x;
    if (p < PP) g_best[p] = 0ull;
}

// ---------------- fully-unrolled compute halves (4 k-steps each) ----------------
__device__ __forceinline__ void mma_block(float* acc, const uint4 af[4], const uint4 bfm[4]) {
    #pragma unroll
    for (int i = 0; i < 4; ++i) {
        #pragma unroll
        for (int r = 0; r < 4; ++r) {
            mma16816(&acc[(i * 8 + 2 * r) * 4],
                     af[i].x, af[i].y, af[i].z, af[i].w, bfm[r].x, bfm[r].y);
            mma16816(&acc[(i * 8 + 2 * r + 1) * 4],
                     af[i].x, af[i].y, af[i].z, af[i].w, bfm[r].z, bfm[r].w);
        }
    }
}

// B = hi variant half: run A-hi and A-lo passes (2 passes over 4 k-steps)
__device__ __forceinline__ void compute_pass2_half(const uint4* A0, const uint4* A1,
                                                   const uint4* Bw, float* acc) {
    #pragma unroll
    for (int s = 0; s < 4; ++s) {
        uint4 bfm[4];
        const uint4* bp = Bw + (s << 9);
        #pragma unroll
        for (int r = 0; r < 4; ++r) bfm[r] = bp[r * 32];
        uint4 af[4];
        #pragma unroll
        for (int i = 0; i < 4; ++i) af[i] = A0[(s * 8 + i) * 32];
        mma_block(acc, af, bfm);
        #pragma unroll
        for (int i = 0; i < 4; ++i) af[i] = A1[(s * 8 + i) * 32];
        mma_block(acc, af, bfm);
    }
}

// B = lo variant half: A-hi pass only (1 pass over 4 k-steps)
__device__ __forceinline__ void compute_pass1_half(const uint4* A0, const uint4* Bw,
                                                   float* acc) {
    #pragma unroll
    for (int s = 0; s < 4; ++s) {
        uint4 bfm[4];
        const uint4* bp = Bw + (s << 9);
        #pragma unroll
        for (int r = 0; r < 4; ++r) bfm[r] = bp[r * 32];
        uint4 af[4];
        #pragma unroll
        for (int i = 0; i < 4; ++i) af[i] = A0[(s * 8 + i) * 32];
        mma_block(acc, af, bfm);
    }
}

// fold tile's acc into running argmax, then zero acc (interleaves into MMA shadow)
__device__ __forceinline__ void fold_zero(float* acc, float* bv, int* bq, int q0, int t2) {
    #pragma unroll
    for (int i = 0; i < 4; ++i)
        #pragma unroll
        for (int j = 0; j < 8; ++j) {
            int qb = q0 + j * 8 + t2;
            #pragma unroll
            for (int c = 0; c < 4; ++c) {
                float v = acc[(i * 8 + j) * 4 + c];
                int slot = i * 2 + (c >> 1);
                int q = qb + (c & 1);
                if (v > bv[slot]) { bv[slot] = v; bq[slot] = q; }
                acc[(i * 8 + j) * 4 + c] = 0.0f;
            }
        }
}

// ---------------- main GEMM + fused argmax ----------------
__global__ void __launch_bounds__(256, 1)
corr_mma_kernel() {
    extern __shared__ char smem[];
    const uint32_t sb = smem_u32(smem);
    const int tid = threadIdx.x, lane = tid & 31, wid = tid >> 5;
    const int wm = wid >> 2, wn = wid & 3;           // 2 m-warps x 4 n-warps
    const int g = lane >> 2, t = lane & 3;
    const int mt = blockIdx.x, ns = blockIdx.y;
    const int tile0 = ns * TPC;

    // barriers: FULL[i] = sb + 16*i (tx-based), FREE[i] = sb + 64 + 16*i (count 256)
    const uint32_t FULL0 = sb + 0,  FULL1 = sb + 16, FULL2 = sb + 32, FULL3 = sb + 48;
    const uint32_t FREE0 = sb + 64, FREE1 = sb + 80, FREE2 = sb + 96, FREE3 = sb + 112;
    if (tid == 0) {
        MBAR_INIT(FULL0, 1); MBAR_INIT(FULL1, 1); MBAR_INIT(FULL2, 1); MBAR_INIT(FULL3, 1);
        MBAR_INIT(FREE0, 256); MBAR_INIT(FREE1, 256);
        MBAR_INIT(FREE2, 256); MBAR_INIT(FREE3, 256);
    }

    // A images (2 variants, 64KB) -> resident SMEM, coalesced
    {
        const uint4* srcA = gA4 + (size_t)mt * 2 * 2048;
        uint4* dstA = reinterpret_cast<uint4*>(smem + SMEM_A_OFF);
        #pragma unroll
        for (int i = 0; i < 16; ++i) dstA[i * 256 + tid] = srcA[i * 256 + tid];
    }
    __syncthreads();   // barriers init + A visible to all

    const char* gb = reinterpret_cast<const char*>(gB4);
    // prologue: fill all 4 ring buffers with tile0's stages (hi.k0, hi.k1, lo.k0, lo.k1)
    if (tid == 0) {
        size_t ibase = (size_t)(tile0 * 2) * B_IMG_BYTES;
        issue_cp(sb + SMEM_B_OFF + 0 * B_HALF_BYTES, gb + ibase,                               FULL0);
        issue_cp(sb + SMEM_B_OFF + 1 * B_HALF_BYTES, gb + ibase + B_HALF_BYTES,                FULL1);
        issue_cp(sb + SMEM_B_OFF + 2 * B_HALF_BYTES, gb + ibase + B_IMG_BYTES,                 FULL2);
        issue_cp(sb + SMEM_B_OFF + 3 * B_HALF_BYTES, gb + ibase + B_IMG_BYTES + B_HALF_BYTES,  FULL3);
    }

    // hoisted per-warp fragment bases
    const uint4* A0 = reinterpret_cast<const uint4*>(smem + SMEM_A_OFF) + (4 * wm) * 32 + lane;
    const uint4* A1 = reinterpret_cast<const uint4*>(smem + SMEM_A_OFF + A_IMG_BYTES) +
                      (4 * wm) * 32 + lane;
    const uint4* B0 = reinterpret_cast<const uint4*>(smem + SMEM_B_OFF) + (wn << 7) + lane;
    const uint4* B1 = B0 + (B_HALF_BYTES / 16);
    const uint4* B2 = B1 + (B_HALF_BYTES / 16);
    const uint4* B3 = B2 + (B_HALF_BYTES / 16);

    float acc[128];
    float bv[8];
    int bq[8];
    #pragma unroll
    for (int i = 0; i < 8; ++i) { bv[i] = -3.402823466e38f; bq[i] = 0; }

    const int t2 = 2 * t;

    for (int tile = 0; tile < TPC; ++tile) {
        const uint32_t ph = (uint32_t)(tile & 1);
        const bool refill = (tile + 1 < TPC);
        const size_t nbase = (size_t)((tile0 + tile + 1) * 2) * B_IMG_BYTES;

        // fold previous tile (or zero-init) BEFORE the wait — hides in wait/MMA shadow
        if (tile == 0) {
            #pragma unroll
            for (int i = 0; i < 128; ++i) acc[i] = 0.0f;
        } else {
            fold_zero(acc, bv, bq, (tile0 + tile - 1) * 256 + wn * 64, t2);
        }

        // stage 0: buf0 = (hi, k0..63)
        mbar_wait(FULL0, ph);
        compute_pass2_half(A0, A1, B0, acc);
        MBAR_ARRIVE(FREE0);
        if (tid == 0 && refill) {
            mbar_wait(FREE0, ph);
            issue_cp(sb + SMEM_B_OFF + 0 * B_HALF_BYTES, gb + nbase, FULL0);
        }

        // stage 1: buf1 = (hi, k64..127)
        mbar_wait(FULL1, ph);
        compute_pass2_half(A0 + 1024, A1 + 1024, B1, acc);
        MBAR_ARRIVE(FREE1);
        if (tid == 0 && refill) {
            mbar_wait(FREE1, ph);
            issue_cp(sb + SMEM_B_OFF + 1 * B_HALF_BYTES, gb + nbase + B_HALF_BYTES, FULL1);
        }

        // stage 2: buf2 = (lo, k0..63)
        mbar_wait(FULL2, ph);
        compute_pass1_half(A0, B2, acc);
        MBAR_ARRIVE(FREE2);
        if (tid == 0 && refill) {
            mbar_wait(FREE2, ph);
            issue_cp(sb + SMEM_B_OFF + 2 * B_HALF_BYTES, gb + nbase + B_IMG_BYTES, FULL2);
        }

        // stage 3: buf3 = (lo, k64..127)
        mbar_wait(FULL3, ph);
        compute_pass1_half(A0 + 1024, B3, acc);
        MBAR_ARRIVE(FREE3);
        if (tid == 0 && refill) {
            mbar_wait(FREE3, ph);
            issue_cp(sb + SMEM_B_OFF + 3 * B_HALF_BYTES,
                     gb + nbase + B_IMG_BYTES + B_HALF_BYTES, FULL3);
        }
    }

    // final tile's fold
    fold_zero(acc, bv, bq, (tile0 + TPC - 1) * 256 + wn * 64, t2);

    // reduce across the 4 lanes sharing the same rows (t = 0..3)
    #pragma unroll
    for (int off = 1; off < 4; off <<= 1) {
        #pragma unroll
        for (int s2 = 0; s2 < 8; ++s2) {
            float ov = __shfl_xor_sync(0xFFFFFFFFu, bv[s2], off);
            int oq = __shfl_xor_sync(0xFFFFFFFFu, bq[s2], off);
            if (ov > bv[s2] || (ov == bv[s2] && oq < bq[s2])) { bv[s2] = ov; bq[s2] = oq; }
        }
    }
    if (t == 0) {
        #pragma unroll
        for (int s2 = 0; s2 < 8; ++s2) {
            int row = mt * 128 + (4 * wm + (s2 >> 1)) * 16 + g + (s2 & 1) * 8;
            unsigned long long pk = ((unsigned long long)fkey(bv[s2]) << 32) |
                                    (0xFFFFFFFFu - (unsigned)bq[s2]);
            atomicMax(&g_best[row], pk);
        }
    }
}

// ---------------- decode ----------------
__global__ void decode_kernel(float* __restrict__ out,
                              const int* __restrict__ sxp,
                              const int* __restrict__ syp) {
    int p = blockIdx.x * blockDim.x + threadIdx.x;
    if (p >= PP) return;
    int sx = sxp ? *sxp : 4;
    int sy = syp ? *syp : 4;

    unsigned long long pk = g_best[p];
    unsigned int key = (unsigned int)(pk >> 32);
    unsigned int idx = 0xFFFFFFFFu - (unsigned int)(pk & 0xFFFFFFFFu);
    float val = (key & 0x80000000u) ? __uint_as_float(key ^ 0x80000000u)
                                    : __uint_as_float(~key);
    int h = p / WW, w = p % WW;
    int i = (int)(idx / WRR), j = (int)(idx % WRR);

    out[2 * p + 0]  = (float)(w - j * sx);
    out[2 * p + 1]  = (float)(h - i * sy);
    out[2 * PP + p] = val;
}

// ---------------- launch ----------------
extern "C" void kernel_launch(void* const* d_in, const int* in_sizes, int n_in,
                              void* d_out, int out_size) {
    const float* fl = (const float*)d_in[0];
    const float* fr = (const float*)d_in[1];
    const int* sxp = (n_in > 2) ? (const int*)d_in[2] : nullptr;
    const int* syp = (n_in > 3) ? (const int*)d_in[3] : nullptr;
    float* out = (float*)d_out;
    (void)in_sizes; (void)out_size;

    cudaFuncSetAttribute(corr_mma_kernel,
                         cudaFuncAttributeMaxDynamicSharedMemorySize, SMEM_TOTAL);

    splitA_kernel<<<768, 256>>>(fl);
    splitB_kernel<<<768, 256>>>(fr);
    init_best_kernel<<<(PP + 255) / 256, 256>>>();
    corr_mma_kernel<<<dim3(PP / BM, NS), 256, SMEM_TOTAL>>>();
    decode_kernel<<<(PP + 255) / 256, 256>>>(out, sxp, syp);
}